// round 14
// baseline (speedup 1.0000x reference)
#include <cuda_runtime.h>
#include <cstdint>

#define N_CATS 8
#define NBLOCKS 148            // 1 CTA per SM
#define NTHREADS 512           // 16 warps
#define DEPTH 6                // pipeline stages (221 KB in flight per SM)
#define STAGE_ELEMS 1024
#define LOGIT_BYTES (STAGE_ELEMS * 32)          // 32768
#define TGT_BYTES   (STAGE_ELEMS * 4)           // 4096
#define SLOT_BYTES  (LOGIT_BYTES + TGT_BYTES)   // 36864
#define SMEM_BAR_OFF (DEPTH * SLOT_BYTES)       // 221184
#define SMEM_TOTAL   (SMEM_BAR_OFF + DEPTH * 8 + 8)

// Device-global scratch: 8x8 confusion-matrix counts + arrival ticket.
__device__ unsigned int g_cm[64];
__device__ unsigned int g_done;

#define MBAR_INIT(addr, count) \
    asm volatile("mbarrier.init.shared.b64 [%0], %1;" :: "r"(addr), "r"(count) : "memory")
#define MBAR_EXPECT_TX(addr, bytes) \
    asm volatile("mbarrier.arrive.expect_tx.shared.b64 _, [%0], %1;" :: "r"(addr), "r"(bytes) : "memory")
#define BULK_G2S(dst, src, bytes, mbar) \
    asm volatile("cp.async.bulk.shared::cluster.global.mbarrier::complete_tx::bytes [%0], [%1], %2, [%3];" \
                 :: "r"(dst), "l"(src), "r"(bytes), "r"(mbar) : "memory")

__device__ __forceinline__ void mbar_wait_parity(uint32_t mbar, uint32_t parity) {
    uint32_t done;
    asm volatile(
        "{\n\t.reg .pred p;\n\t"
        "mbarrier.try_wait.parity.acquire.cta.shared::cta.b64 p, [%1], %2;\n\t"
        "selp.b32 %0, 1, 0, p;\n\t}"
        : "=r"(done) : "r"(mbar), "r"(parity) : "memory");
    if (!done) {
        asm volatile(
            "{\n\t.reg .pred P1;\n\t"
            "WAIT_LOOP_%=:\n\t"
            "mbarrier.try_wait.parity.acquire.cta.shared::cta.b64 P1, [%0], %1, 0x989680;\n\t"
            "@P1 bra.uni WAIT_DONE_%=;\n\t"
            "bra.uni WAIT_LOOP_%=;\n\t"
            "WAIT_DONE_%=:\n\t}"
            :: "r"(mbar), "r"(parity) : "memory");
    }
}

// Process one 32-element block held dense across the warp (from SMEM).
__device__ __forceinline__ void process32(
    float4 A, float4 B, int tv, int lane,
    const unsigned* __restrict__ sgn, unsigned& cL, unsigned& cH)
{
    int aA = 0; float mA = A.x;
    if (A.y > mA) { mA = A.y; aA = 1; }
    if (A.z > mA) { mA = A.z; aA = 2; }
    if (A.w > mA) { mA = A.w; aA = 3; }
    int aB = 0; float mB = B.x;
    if (B.y > mB) { mB = B.y; aB = 1; }
    if (B.z > mB) { mB = B.z; aB = 2; }
    if (B.w > mB) { mB = B.w; aB = 3; }

    float mAp = __shfl_xor_sync(0xffffffffu, mA, 1);
    int   aAp = __shfl_xor_sync(0xffffffffu, aA, 1);
    float mBp = __shfl_xor_sync(0xffffffffu, mB, 1);
    int   aBp = __shfl_xor_sync(0xffffffffu, aB, 1);

    int pred;
    if (lane & 1) pred = (mB  > mBp) ? (4 + aB)  : aBp;
    else          pred = (mAp > mA ) ? (4 + aAp) : aA;

    unsigned bin = (unsigned)tv * 8u + (unsigned)pred;
    bool v = ((unsigned)(tv - 1) < 7u);

    unsigned m = __ballot_sync(0xffffffffu, v);
    #pragma unroll
    for (int k = 0; k < 5; k++) {
        unsigned mb = __ballot_sync(0xffffffffu, (bin >> k) & 1u);
        m &= mb ^ sgn[k];
    }
    unsigned mb5 = __ballot_sync(0xffffffffu, (bin >> 5) & 1u);
    cL += __popc(m & ~mb5);
    cH += __popc(m & mb5);
}

__global__ __launch_bounds__(NTHREADS, 1) void qwk_tma_kernel(
    const float* __restrict__ logits,
    const int* __restrict__ targets,
    float* __restrict__ out,
    int n_elems)                          // multiple of STAGE_ELEMS
{
    extern __shared__ char smem[];
    __shared__ unsigned s_cm[64];
    __shared__ bool s_is_last;

    const int tid = threadIdx.x;
    const int lane = tid & 31;
    const int wid = tid >> 5;             // 0..15
    const uint32_t smem_base = (uint32_t)__cvta_generic_to_shared(smem);

    if (tid < 64) s_cm[tid] = 0u;
    if (tid == 0) {
        #pragma unroll
        for (int i = 0; i < DEPTH; i++)
            MBAR_INIT(smem_base + SMEM_BAR_OFF + i * 8, 1);
        asm volatile("fence.proxy.async.shared::cta;" ::: "memory");
    }
    __syncthreads();

    unsigned sgn[5];
    #pragma unroll
    for (int k = 0; k < 5; k++)
        sgn[k] = (((unsigned)lane >> k) & 1u) - 1u;

    unsigned cL = 0u, cH = 0u;

    const int total_stages = n_elems / STAGE_ELEMS;     // 8192
    const int bx = blockIdx.x;
    const int nloc = (total_stages - bx + NBLOCKS - 1) / NBLOCKS;

    // Prologue: fill the pipeline.
    if (tid == 0) {
        int pre = nloc < DEPTH ? nloc : DEPTH;
        for (int i = 0; i < pre; i++) {
            int g = bx + i * NBLOCKS;
            uint32_t mbar = smem_base + SMEM_BAR_OFF + i * 8;
            uint32_t dstL = smem_base + i * SLOT_BYTES;
            uint32_t dstT = dstL + LOGIT_BYTES;
            MBAR_EXPECT_TX(mbar, SLOT_BYTES);
            BULK_G2S(dstL, (const void*)(logits + (size_t)g * STAGE_ELEMS * 8), LOGIT_BYTES, mbar);
            BULK_G2S(dstT, (const void*)(targets + (size_t)g * STAGE_ELEMS), TGT_BYTES, mbar);
        }
    }

    const int el_off = (lane >> 1) + ((lane & 1) << 4);

    int slot = 0;          // sl % DEPTH, tracked incrementally
    int parity = 0;        // flips each slot wrap
    for (int sl = 0; sl < nloc; sl++) {
        uint32_t mbar = smem_base + SMEM_BAR_OFF + slot * 8;
        mbar_wait_parity(mbar, (uint32_t)parity);

        const float4* sL = (const float4*)(smem + slot * SLOT_BYTES);
        const int*    sT = (const int*)(smem + slot * SLOT_BYTES + LOGIT_BYTES);

        // 16 warps x 64 elements = 1024 per stage.
        int base = wid * 64;
        float4 A0 = sL[2 * base +       lane];
        float4 B0 = sL[2 * base + 32 +  lane];
        float4 A1 = sL[2 * base + 64 +  lane];
        float4 B1 = sL[2 * base + 96 +  lane];
        int t0 = sT[base +      el_off];
        int t1 = sT[base + 32 + el_off];

        process32(A0, B0, t0, lane, sgn, cL, cH);
        process32(A1, B1, t1, lane, sgn, cL, cH);

        __syncthreads();   // everyone done with this slot

        if (tid == 0 && sl + DEPTH < nloc) {
            int g = bx + (sl + DEPTH) * NBLOCKS;
            uint32_t dstL = smem_base + slot * SLOT_BYTES;
            uint32_t dstT = dstL + LOGIT_BYTES;
            MBAR_EXPECT_TX(mbar, SLOT_BYTES);
            BULK_G2S(dstL, (const void*)(logits + (size_t)g * STAGE_ELEMS * 8), LOGIT_BYTES, mbar);
            BULK_G2S(dstT, (const void*)(targets + (size_t)g * STAGE_ELEMS), TGT_BYTES, mbar);
        }

        if (++slot == DEPTH) { slot = 0; parity ^= 1; }
    }

    // Per-warp flush: 2 shared atomics per lane, once per kernel.
    if (cL) atomicAdd(&s_cm[lane], cL);
    if (cH) atomicAdd(&s_cm[lane + 32], cH);
    __syncthreads();

    // Block flush to global.
    if (tid < 64) {
        unsigned int c = s_cm[tid];
        if (c) atomicAdd(&g_cm[tid], c);
    }

    // Ticket: last block to arrive finalizes.
    __threadfence();
    __syncthreads();
    if (tid == 0) {
        unsigned int rank = atomicAdd(&g_done, 1u);
        s_is_last = (rank == gridDim.x - 1);
    }
    __syncthreads();
    if (!s_is_last) return;

    if (tid == 0) {
        __threadfence();

        float cm[64];
        float n = 0.0f;
        #pragma unroll
        for (int i = 0; i < 64; i++) {
            unsigned int c = atomicAdd(&g_cm[i], 0u);
            cm[i] = (float)c;
            n += cm[i];
        }

        float loss;
        if (n == 0.0f) {
            loss = 0.0f;
        } else {
            float inv_n = 1.0f / n;
            #pragma unroll
            for (int i = 0; i < 64; i++) cm[i] *= inv_n;

            float mt[8], mp[8];
            #pragma unroll
            for (int i = 0; i < 8; i++) { mt[i] = 0.0f; mp[i] = 0.0f; }
            #pragma unroll
            for (int i = 0; i < 8; i++)
                #pragma unroll
                for (int jj = 0; jj < 8; jj++) {
                    mt[i] += cm[i * 8 + jj];
                    mp[jj] += cm[i * 8 + jj];
                }

            const float inv_d2 = 1.0f / 49.0f;
            float num = 0.0f, den = 0.0f;
            #pragma unroll
            for (int i = 0; i < 8; i++)
                #pragma unroll
                for (int jj = 0; jj < 8; jj++) {
                    float d = (float)(i - jj);
                    float w = 1.0f - d * d * inv_d2;
                    num += w * cm[i * 8 + jj];
                    den += w * mt[i] * mp[jj];
                }

            float qwk = (den == 0.0f) ? 0.0f : (num / den);
            loss = 1.0f - qwk;
        }
        out[0] = loss;

        #pragma unroll
        for (int i = 0; i < 64; i++) g_cm[i] = 0u;
        g_done = 0u;
        __threadfence();
    }
}

extern "C" void kernel_launch(void* const* d_in, const int* in_sizes, int n_in,
                              void* d_out, int out_size) {
    const float* logits = (const float*)d_in[0];
    const int* targets = (const int*)d_in[1];
    float* out = (float*)d_out;
    int n_elems = in_sizes[1];       // 2048*4096, multiple of 1024

    cudaFuncSetAttribute(qwk_tma_kernel,
                         cudaFuncAttributeMaxDynamicSharedMemorySize, SMEM_TOTAL);
    qwk_tma_kernel<<<NBLOCKS, NTHREADS, SMEM_TOTAL>>>(logits, targets, out, n_elems);
}

// round 15
// speedup vs baseline: 1.0267x; 1.0267x over previous
#include <cuda_runtime.h>
#include <cstdint>

#define N_CATS 8
#define NBLOCKS 296            // 2 CTAs per SM
#define NTHREADS 256           // 8 warps
#define DEPTH 3                // stages per CTA (2 in flight while consuming)
#define STAGE_ELEMS 1024
#define LOGIT_BYTES (STAGE_ELEMS * 32)          // 32768
#define TGT_BYTES   (STAGE_ELEMS * 4)           // 4096
#define SLOT_BYTES  (LOGIT_BYTES + TGT_BYTES)   // 36864
#define SMEM_BAR_OFF (DEPTH * SLOT_BYTES)       // 110592
#define SMEM_TOTAL   (SMEM_BAR_OFF + DEPTH * 8 + 8)   // 110624

// Device-global scratch: 8x8 confusion-matrix counts + arrival ticket.
__device__ unsigned int g_cm[64];
__device__ unsigned int g_done;

#define MBAR_INIT(addr, count) \
    asm volatile("mbarrier.init.shared.b64 [%0], %1;" :: "r"(addr), "r"(count) : "memory")
#define MBAR_EXPECT_TX(addr, bytes) \
    asm volatile("mbarrier.arrive.expect_tx.shared.b64 _, [%0], %1;" :: "r"(addr), "r"(bytes) : "memory")
#define BULK_G2S(dst, src, bytes, mbar) \
    asm volatile("cp.async.bulk.shared::cluster.global.mbarrier::complete_tx::bytes [%0], [%1], %2, [%3];" \
                 :: "r"(dst), "l"(src), "r"(bytes), "r"(mbar) : "memory")

__device__ __forceinline__ void mbar_wait_parity(uint32_t mbar, uint32_t parity) {
    uint32_t done;
    asm volatile(
        "{\n\t.reg .pred p;\n\t"
        "mbarrier.try_wait.parity.acquire.cta.shared::cta.b64 p, [%1], %2;\n\t"
        "selp.b32 %0, 1, 0, p;\n\t}"
        : "=r"(done) : "r"(mbar), "r"(parity) : "memory");
    if (!done) {
        asm volatile(
            "{\n\t.reg .pred P1;\n\t"
            "WAIT_LOOP_%=:\n\t"
            "mbarrier.try_wait.parity.acquire.cta.shared::cta.b64 P1, [%0], %1, 0x989680;\n\t"
            "@P1 bra.uni WAIT_DONE_%=;\n\t"
            "bra.uni WAIT_LOOP_%=;\n\t"
            "WAIT_DONE_%=:\n\t}"
            :: "r"(mbar), "r"(parity) : "memory");
    }
}

// Process one 32-element block held dense across the warp (from SMEM).
__device__ __forceinline__ void process32(
    float4 A, float4 B, int tv, int lane,
    const unsigned* __restrict__ sgn, unsigned& cL, unsigned& cH)
{
    int aA = 0; float mA = A.x;
    if (A.y > mA) { mA = A.y; aA = 1; }
    if (A.z > mA) { mA = A.z; aA = 2; }
    if (A.w > mA) { mA = A.w; aA = 3; }
    int aB = 0; float mB = B.x;
    if (B.y > mB) { mB = B.y; aB = 1; }
    if (B.z > mB) { mB = B.z; aB = 2; }
    if (B.w > mB) { mB = B.w; aB = 3; }

    float mAp = __shfl_xor_sync(0xffffffffu, mA, 1);
    int   aAp = __shfl_xor_sync(0xffffffffu, aA, 1);
    float mBp = __shfl_xor_sync(0xffffffffu, mB, 1);
    int   aBp = __shfl_xor_sync(0xffffffffu, aB, 1);

    int pred;
    if (lane & 1) pred = (mB  > mBp) ? (4 + aB)  : aBp;
    else          pred = (mAp > mA ) ? (4 + aAp) : aA;

    unsigned bin = (unsigned)tv * 8u + (unsigned)pred;
    bool v = ((unsigned)(tv - 1) < 7u);

    unsigned m = __ballot_sync(0xffffffffu, v);
    #pragma unroll
    for (int k = 0; k < 5; k++) {
        unsigned mb = __ballot_sync(0xffffffffu, (bin >> k) & 1u);
        m &= mb ^ sgn[k];
    }
    unsigned mb5 = __ballot_sync(0xffffffffu, (bin >> 5) & 1u);
    cL += __popc(m & ~mb5);
    cH += __popc(m & mb5);
}

__global__ __launch_bounds__(NTHREADS, 2) void qwk_tma_kernel(
    const float* __restrict__ logits,
    const int* __restrict__ targets,
    float* __restrict__ out,
    int n_elems)                          // multiple of STAGE_ELEMS
{
    extern __shared__ char smem[];
    __shared__ unsigned s_cm[64];
    __shared__ bool s_is_last;

    const int tid = threadIdx.x;
    const int lane = tid & 31;
    const int wid = tid >> 5;             // 0..7
    const uint32_t smem_base = (uint32_t)__cvta_generic_to_shared(smem);

    if (tid < 64) s_cm[tid] = 0u;
    if (tid == 0) {
        #pragma unroll
        for (int i = 0; i < DEPTH; i++)
            MBAR_INIT(smem_base + SMEM_BAR_OFF + i * 8, 1);
        asm volatile("fence.proxy.async.shared::cta;" ::: "memory");
    }
    __syncthreads();

    unsigned sgn[5];
    #pragma unroll
    for (int k = 0; k < 5; k++)
        sgn[k] = (((unsigned)lane >> k) & 1u) - 1u;

    unsigned cL = 0u, cH = 0u;

    const int total_stages = n_elems / STAGE_ELEMS;     // 8192
    const int bx = blockIdx.x;
    const int nloc = (total_stages - bx + NBLOCKS - 1) / NBLOCKS;

    // Prologue: fill the pipeline.
    if (tid == 0) {
        int pre = nloc < DEPTH ? nloc : DEPTH;
        for (int i = 0; i < pre; i++) {
            int g = bx + i * NBLOCKS;
            uint32_t mbar = smem_base + SMEM_BAR_OFF + i * 8;
            uint32_t dstL = smem_base + i * SLOT_BYTES;
            uint32_t dstT = dstL + LOGIT_BYTES;
            MBAR_EXPECT_TX(mbar, SLOT_BYTES);
            BULK_G2S(dstL, (const void*)(logits + (size_t)g * STAGE_ELEMS * 8), LOGIT_BYTES, mbar);
            BULK_G2S(dstT, (const void*)(targets + (size_t)g * STAGE_ELEMS), TGT_BYTES, mbar);
        }
    }

    const int el_off = (lane >> 1) + ((lane & 1) << 4);

    int slot = 0;          // sl % DEPTH, tracked incrementally
    int parity = 0;        // flips each slot wrap
    for (int sl = 0; sl < nloc; sl++) {
        uint32_t mbar = smem_base + SMEM_BAR_OFF + slot * 8;
        mbar_wait_parity(mbar, (uint32_t)parity);

        const float4* sL = (const float4*)(smem + slot * SLOT_BYTES);
        const int*    sT = (const int*)(smem + slot * SLOT_BYTES + LOGIT_BYTES);

        // 8 warps x 128 elements = 1024 per stage.
        int base = wid * 128;
        #pragma unroll
        for (int q = 0; q < 4; q++) {
            int eb = base + q * 32;
            float4 A = sL[2 * eb +      lane];
            float4 B = sL[2 * eb + 32 + lane];
            int t = sT[eb + el_off];
            process32(A, B, t, lane, sgn, cL, cH);
        }

        __syncthreads();   // everyone done with this slot

        if (tid == 0 && sl + DEPTH < nloc) {
            int g = bx + (sl + DEPTH) * NBLOCKS;
            uint32_t dstL = smem_base + slot * SLOT_BYTES;
            uint32_t dstT = dstL + LOGIT_BYTES;
            MBAR_EXPECT_TX(mbar, SLOT_BYTES);
            BULK_G2S(dstL, (const void*)(logits + (size_t)g * STAGE_ELEMS * 8), LOGIT_BYTES, mbar);
            BULK_G2S(dstT, (const void*)(targets + (size_t)g * STAGE_ELEMS), TGT_BYTES, mbar);
        }

        if (++slot == DEPTH) { slot = 0; parity ^= 1; }
    }

    // Per-warp flush: 2 shared atomics per lane, once per kernel.
    if (cL) atomicAdd(&s_cm[lane], cL);
    if (cH) atomicAdd(&s_cm[lane + 32], cH);
    __syncthreads();

    // Block flush to global.
    if (tid < 64) {
        unsigned int c = s_cm[tid];
        if (c) atomicAdd(&g_cm[tid], c);
    }

    // Ticket: last block to arrive finalizes.
    __threadfence();
    __syncthreads();
    if (tid == 0) {
        unsigned int rank = atomicAdd(&g_done, 1u);
        s_is_last = (rank == gridDim.x - 1);
    }
    __syncthreads();
    if (!s_is_last) return;

    if (tid == 0) {
        __threadfence();

        float cm[64];
        float n = 0.0f;
        #pragma unroll
        for (int i = 0; i < 64; i++) {
            unsigned int c = atomicAdd(&g_cm[i], 0u);
            cm[i] = (float)c;
            n += cm[i];
        }

        float loss;
        if (n == 0.0f) {
            loss = 0.0f;
        } else {
            float inv_n = 1.0f / n;
            #pragma unroll
            for (int i = 0; i < 64; i++) cm[i] *= inv_n;

            float mt[8], mp[8];
            #pragma unroll
            for (int i = 0; i < 8; i++) { mt[i] = 0.0f; mp[i] = 0.0f; }
            #pragma unroll
            for (int i = 0; i < 8; i++)
                #pragma unroll
                for (int jj = 0; jj < 8; jj++) {
                    mt[i] += cm[i * 8 + jj];
                    mp[jj] += cm[i * 8 + jj];
                }

            const float inv_d2 = 1.0f / 49.0f;
            float num = 0.0f, den = 0.0f;
            #pragma unroll
            for (int i = 0; i < 8; i++)
                #pragma unroll
                for (int jj = 0; jj < 8; jj++) {
                    float d = (float)(i - jj);
                    float w = 1.0f - d * d * inv_d2;
                    num += w * cm[i * 8 + jj];
                    den += w * mt[i] * mp[jj];
                }

            float qwk = (den == 0.0f) ? 0.0f : (num / den);
            loss = 1.0f - qwk;
        }
        out[0] = loss;

        #pragma unroll
        for (int i = 0; i < 64; i++) g_cm[i] = 0u;
        g_done = 0u;
        __threadfence();
    }
}

extern "C" void kernel_launch(void* const* d_in, const int* in_sizes, int n_in,
                              void* d_out, int out_size) {
    const float* logits = (const float*)d_in[0];
    const int* targets = (const int*)d_in[1];
    float* out = (float*)d_out;
    int n_elems = in_sizes[1];       // 2048*4096, multiple of 1024

    cudaFuncSetAttribute(qwk_tma_kernel,
                         cudaFuncAttributeMaxDynamicSharedMemorySize, SMEM_TOTAL);
    qwk_tma_kernel<<<NBLOCKS, NTHREADS, SMEM_TOTAL>>>(logits, targets, out, n_elems);
}

// round 16
// speedup vs baseline: 1.0798x; 1.0517x over previous
#include <cuda_runtime.h>
#include <cstdint>

#define N_CATS 8
#define NBLOCKS 148            // 1 CTA per SM
#define NTHREADS 512           // 16 warps
#define DEPTH 4                // pipeline stages
#define STAGE_ELEMS 1024
#define LOGIT_BYTES (STAGE_ELEMS * 32)          // 32768
#define TGT_BYTES   (STAGE_ELEMS * 4)           // 4096
#define SLOT_BYTES  (LOGIT_BYTES + TGT_BYTES)   // 36864
#define SMEM_BAR_OFF (DEPTH * SLOT_BYTES)       // 147456
#define SMEM_TOTAL   (SMEM_BAR_OFF + DEPTH * 8 + 8)

// Device-global scratch: 8x8 confusion-matrix counts + arrival ticket.
__device__ unsigned int g_cm[64];
__device__ unsigned int g_done;

#define MBAR_INIT(addr, count) \
    asm volatile("mbarrier.init.shared.b64 [%0], %1;" :: "r"(addr), "r"(count) : "memory")
#define MBAR_EXPECT_TX(addr, bytes) \
    asm volatile("mbarrier.arrive.expect_tx.shared.b64 _, [%0], %1;" :: "r"(addr), "r"(bytes) : "memory")
#define BULK_G2S(dst, src, bytes, mbar) \
    asm volatile("cp.async.bulk.shared::cluster.global.mbarrier::complete_tx::bytes [%0], [%1], %2, [%3];" \
                 :: "r"(dst), "l"(src), "r"(bytes), "r"(mbar) : "memory")

__device__ __forceinline__ void mbar_wait_parity(uint32_t mbar, uint32_t parity) {
    uint32_t done;
    asm volatile(
        "{\n\t.reg .pred p;\n\t"
        "mbarrier.try_wait.parity.acquire.cta.shared::cta.b64 p, [%1], %2;\n\t"
        "selp.b32 %0, 1, 0, p;\n\t}"
        : "=r"(done) : "r"(mbar), "r"(parity) : "memory");
    if (!done) {
        asm volatile(
            "{\n\t.reg .pred P1;\n\t"
            "WAIT_LOOP_%=:\n\t"
            "mbarrier.try_wait.parity.acquire.cta.shared::cta.b64 P1, [%0], %1, 0x989680;\n\t"
            "@P1 bra.uni WAIT_DONE_%=;\n\t"
            "bra.uni WAIT_LOOP_%=;\n\t"
            "WAIT_DONE_%=:\n\t}"
            :: "r"(mbar), "r"(parity) : "memory");
    }
}

// Process one 32-element block held dense across the warp (from SMEM).
__device__ __forceinline__ void process32(
    float4 A, float4 B, int tv, int lane,
    const unsigned* __restrict__ sgn, unsigned& cL, unsigned& cH)
{
    int aA = 0; float mA = A.x;
    if (A.y > mA) { mA = A.y; aA = 1; }
    if (A.z > mA) { mA = A.z; aA = 2; }
    if (A.w > mA) { mA = A.w; aA = 3; }
    int aB = 0; float mB = B.x;
    if (B.y > mB) { mB = B.y; aB = 1; }
    if (B.z > mB) { mB = B.z; aB = 2; }
    if (B.w > mB) { mB = B.w; aB = 3; }

    float mAp = __shfl_xor_sync(0xffffffffu, mA, 1);
    int   aAp = __shfl_xor_sync(0xffffffffu, aA, 1);
    float mBp = __shfl_xor_sync(0xffffffffu, mB, 1);
    int   aBp = __shfl_xor_sync(0xffffffffu, aB, 1);

    int pred;
    if (lane & 1) pred = (mB  > mBp) ? (4 + aB)  : aBp;
    else          pred = (mAp > mA ) ? (4 + aAp) : aA;

    unsigned bin = (unsigned)tv * 8u + (unsigned)pred;
    bool v = ((unsigned)(tv - 1) < 7u);

    unsigned m = __ballot_sync(0xffffffffu, v);
    #pragma unroll
    for (int k = 0; k < 5; k++) {
        unsigned mb = __ballot_sync(0xffffffffu, (bin >> k) & 1u);
        m &= mb ^ sgn[k];
    }
    unsigned mb5 = __ballot_sync(0xffffffffu, (bin >> 5) & 1u);
    cL += __popc(m & ~mb5);
    cH += __popc(m & mb5);
}

__global__ __launch_bounds__(NTHREADS, 1) void qwk_tma_kernel(
    const float* __restrict__ logits,
    const int* __restrict__ targets,
    float* __restrict__ out,
    int n_elems)                          // multiple of STAGE_ELEMS
{
    extern __shared__ char smem[];
    __shared__ unsigned s_cm[64];
    __shared__ bool s_is_last;

    const int tid = threadIdx.x;
    const int lane = tid & 31;
    const int wid = tid >> 5;             // 0..15
    const uint32_t smem_base = (uint32_t)__cvta_generic_to_shared(smem);

    if (tid < 64) s_cm[tid] = 0u;
    if (tid == 0) {
        #pragma unroll
        for (int i = 0; i < DEPTH; i++)
            MBAR_INIT(smem_base + SMEM_BAR_OFF + i * 8, 1);
        asm volatile("fence.proxy.async.shared::cta;" ::: "memory");
    }
    __syncthreads();

    unsigned sgn[5];
    #pragma unroll
    for (int k = 0; k < 5; k++)
        sgn[k] = (((unsigned)lane >> k) & 1u) - 1u;

    unsigned cL = 0u, cH = 0u;

    const int total_stages = n_elems / STAGE_ELEMS;     // 8192
    const int bx = blockIdx.x;
    const int nloc = (total_stages - bx + NBLOCKS - 1) / NBLOCKS;

    // Prologue: fill the pipeline.
    if (tid == 0) {
        int pre = nloc < DEPTH ? nloc : DEPTH;
        for (int i = 0; i < pre; i++) {
            int g = bx + i * NBLOCKS;
            uint32_t mbar = smem_base + SMEM_BAR_OFF + i * 8;
            uint32_t dstL = smem_base + i * SLOT_BYTES;
            uint32_t dstT = dstL + LOGIT_BYTES;
            MBAR_EXPECT_TX(mbar, SLOT_BYTES);
            BULK_G2S(dstL, (const void*)(logits + (size_t)g * STAGE_ELEMS * 8), LOGIT_BYTES, mbar);
            BULK_G2S(dstT, (const void*)(targets + (size_t)g * STAGE_ELEMS), TGT_BYTES, mbar);
        }
    }

    const int el_off = (lane >> 1) + ((lane & 1) << 4);

    for (int sl = 0; sl < nloc; sl++) {
        int slot = sl & (DEPTH - 1);
        uint32_t parity = (sl / DEPTH) & 1;
        uint32_t mbar = smem_base + SMEM_BAR_OFF + slot * 8;
        mbar_wait_parity(mbar, parity);

        const float4* sL = (const float4*)(smem + slot * SLOT_BYTES);
        const int*    sT = (const int*)(smem + slot * SLOT_BYTES + LOGIT_BYTES);

        // 16 warps x 64 elements = 1024 per stage.
        int base = wid * 64;
        float4 A0 = sL[2 * base +       lane];
        float4 B0 = sL[2 * base + 32 +  lane];
        float4 A1 = sL[2 * base + 64 +  lane];
        float4 B1 = sL[2 * base + 96 +  lane];
        int t0 = sT[base +      el_off];
        int t1 = sT[base + 32 + el_off];

        process32(A0, B0, t0, lane, sgn, cL, cH);
        process32(A1, B1, t1, lane, sgn, cL, cH);

        __syncthreads();   // everyone done with this slot

        if (tid == 0 && sl + DEPTH < nloc) {
            int g = bx + (sl + DEPTH) * NBLOCKS;
            uint32_t dstL = smem_base + slot * SLOT_BYTES;
            uint32_t dstT = dstL + LOGIT_BYTES;
            MBAR_EXPECT_TX(mbar, SLOT_BYTES);
            BULK_G2S(dstL, (const void*)(logits + (size_t)g * STAGE_ELEMS * 8), LOGIT_BYTES, mbar);
            BULK_G2S(dstT, (const void*)(targets + (size_t)g * STAGE_ELEMS), TGT_BYTES, mbar);
        }
    }

    // Per-warp flush: 2 shared atomics per lane, once per kernel.
    if (cL) atomicAdd(&s_cm[lane], cL);
    if (cH) atomicAdd(&s_cm[lane + 32], cH);
    __syncthreads();

    // Block flush to global.
    if (tid < 64) {
        unsigned int c = s_cm[tid];
        if (c) atomicAdd(&g_cm[tid], c);
    }

    // Ticket: last block to arrive finalizes.
    __threadfence();
    __syncthreads();
    if (tid == 0) {
        unsigned int rank = atomicAdd(&g_done, 1u);
        s_is_last = (rank == gridDim.x - 1);
    }
    __syncthreads();
    if (!s_is_last) return;

    if (tid == 0) {
        __threadfence();

        float cm[64];
        float n = 0.0f;
        #pragma unroll
        for (int i = 0; i < 64; i++) {
            unsigned int c = atomicAdd(&g_cm[i], 0u);
            cm[i] = (float)c;
            n += cm[i];
        }

        float loss;
        if (n == 0.0f) {
            loss = 0.0f;
        } else {
            float inv_n = 1.0f / n;
            #pragma unroll
            for (int i = 0; i < 64; i++) cm[i] *= inv_n;

            float mt[8], mp[8];
            #pragma unroll
            for (int i = 0; i < 8; i++) { mt[i] = 0.0f; mp[i] = 0.0f; }
            #pragma unroll
            for (int i = 0; i < 8; i++)
                #pragma unroll
                for (int jj = 0; jj < 8; jj++) {
                    mt[i] += cm[i * 8 + jj];
                    mp[jj] += cm[i * 8 + jj];
                }

            const float inv_d2 = 1.0f / 49.0f;
            float num = 0.0f, den = 0.0f;
            #pragma unroll
            for (int i = 0; i < 8; i++)
                #pragma unroll
                for (int jj = 0; jj < 8; jj++) {
                    float d = (float)(i - jj);
                    float w = 1.0f - d * d * inv_d2;
                    num += w * cm[i * 8 + jj];
                    den += w * mt[i] * mp[jj];
                }

            float qwk = (den == 0.0f) ? 0.0f : (num / den);
            loss = 1.0f - qwk;
        }
        out[0] = loss;

        #pragma unroll
        for (int i = 0; i < 64; i++) g_cm[i] = 0u;
        g_done = 0u;
        __threadfence();
    }
}

extern "C" void kernel_launch(void* const* d_in, const int* in_sizes, int n_in,
                              void* d_out, int out_size) {
    const float* logits = (const float*)d_in[0];
    const int* targets = (const int*)d_in[1];
    float* out = (float*)d_out;
    int n_elems = in_sizes[1];       // 2048*4096, multiple of 1024

    cudaFuncSetAttribute(qwk_tma_kernel,
                         cudaFuncAttributeMaxDynamicSharedMemorySize, SMEM_TOTAL);
    qwk_tma_kernel<<<NBLOCKS, NTHREADS, SMEM_TOTAL>>>(logits, targets, out, n_elems);
}

// round 17
// speedup vs baseline: 1.0913x; 1.0107x over previous
#include <cuda_runtime.h>
#include <cstdint>

#define N_CATS 8
#define NBLOCKS 148            // 1 CTA per SM
#define NTHREADS 512           // 16 warps
#define DEPTH 4                // pipeline stages
#define STAGE_ELEMS 1024
#define LOGIT_BYTES (STAGE_ELEMS * 32)          // 32768
#define TGT_BYTES   (STAGE_ELEMS * 4)           // 4096
#define SLOT_BYTES  (LOGIT_BYTES + TGT_BYTES)   // 36864
#define SMEM_BAR_OFF (DEPTH * SLOT_BYTES)       // 147456
#define SMEM_TOTAL   (SMEM_BAR_OFF + DEPTH * 8 + 8)

// Device-global scratch: 8x8 confusion-matrix counts + arrival ticket.
__device__ unsigned int g_cm[64];
__device__ unsigned int g_done;

#define MBAR_INIT(addr, count) \
    asm volatile("mbarrier.init.shared.b64 [%0], %1;" :: "r"(addr), "r"(count) : "memory")
#define MBAR_EXPECT_TX(addr, bytes) \
    asm volatile("mbarrier.arrive.expect_tx.shared.b64 _, [%0], %1;" :: "r"(addr), "r"(bytes) : "memory")
#define BULK_G2S(dst, src, bytes, mbar) \
    asm volatile("cp.async.bulk.shared::cluster.global.mbarrier::complete_tx::bytes [%0], [%1], %2, [%3];" \
                 :: "r"(dst), "l"(src), "r"(bytes), "r"(mbar) : "memory")

__device__ __forceinline__ void mbar_wait_parity(uint32_t mbar, uint32_t parity) {
    uint32_t done;
    asm volatile(
        "{\n\t.reg .pred p;\n\t"
        "mbarrier.try_wait.parity.acquire.cta.shared::cta.b64 p, [%1], %2;\n\t"
        "selp.b32 %0, 1, 0, p;\n\t}"
        : "=r"(done) : "r"(mbar), "r"(parity) : "memory");
    if (!done) {
        asm volatile(
            "{\n\t.reg .pred P1;\n\t"
            "WAIT_LOOP_%=:\n\t"
            "mbarrier.try_wait.parity.acquire.cta.shared::cta.b64 P1, [%0], %1, 0x989680;\n\t"
            "@P1 bra.uni WAIT_DONE_%=;\n\t"
            "bra.uni WAIT_LOOP_%=;\n\t"
            "WAIT_DONE_%=:\n\t}"
            :: "r"(mbar), "r"(parity) : "memory");
    }
}

// Process one 32-element block held dense across the warp (from SMEM).
__device__ __forceinline__ void process32(
    float4 A, float4 B, int tv, int lane,
    const unsigned* __restrict__ sgn, unsigned& cL, unsigned& cH)
{
    int aA = 0; float mA = A.x;
    if (A.y > mA) { mA = A.y; aA = 1; }
    if (A.z > mA) { mA = A.z; aA = 2; }
    if (A.w > mA) { mA = A.w; aA = 3; }
    int aB = 0; float mB = B.x;
    if (B.y > mB) { mB = B.y; aB = 1; }
    if (B.z > mB) { mB = B.z; aB = 2; }
    if (B.w > mB) { mB = B.w; aB = 3; }

    float mAp = __shfl_xor_sync(0xffffffffu, mA, 1);
    int   aAp = __shfl_xor_sync(0xffffffffu, aA, 1);
    float mBp = __shfl_xor_sync(0xffffffffu, mB, 1);
    int   aBp = __shfl_xor_sync(0xffffffffu, aB, 1);

    int pred;
    if (lane & 1) pred = (mB  > mBp) ? (4 + aB)  : aBp;
    else          pred = (mAp > mA ) ? (4 + aAp) : aA;

    unsigned bin = (unsigned)tv * 8u + (unsigned)pred;
    bool v = ((unsigned)(tv - 1) < 7u);

    unsigned m = __ballot_sync(0xffffffffu, v);
    #pragma unroll
    for (int k = 0; k < 5; k++) {
        unsigned mb = __ballot_sync(0xffffffffu, (bin >> k) & 1u);
        m &= mb ^ sgn[k];
    }
    unsigned mb5 = __ballot_sync(0xffffffffu, (bin >> 5) & 1u);
    cL += __popc(m & ~mb5);
    cH += __popc(m & mb5);
}

__global__ __launch_bounds__(NTHREADS, 1) void qwk_tma_kernel(
    const float* __restrict__ logits,
    const int* __restrict__ targets,
    float* __restrict__ out,
    int n_elems)                          // multiple of STAGE_ELEMS
{
    extern __shared__ char smem[];
    __shared__ unsigned s_cm[64];
    __shared__ bool s_is_last;

    const int tid = threadIdx.x;
    const int lane = tid & 31;
    const int wid = tid >> 5;             // 0..15
    const uint32_t smem_base = (uint32_t)__cvta_generic_to_shared(smem);

    if (tid < 64) s_cm[tid] = 0u;
    if (tid == 0) {
        #pragma unroll
        for (int i = 0; i < DEPTH; i++)
            MBAR_INIT(smem_base + SMEM_BAR_OFF + i * 8, 1);
        asm volatile("fence.proxy.async.shared::cta;" ::: "memory");
    }
    __syncthreads();

    unsigned sgn[5];
    #pragma unroll
    for (int k = 0; k < 5; k++)
        sgn[k] = (((unsigned)lane >> k) & 1u) - 1u;

    unsigned cL = 0u, cH = 0u;

    const int total_stages = n_elems / STAGE_ELEMS;     // 8192
    const int bx = blockIdx.x;
    const int nloc = (total_stages - bx + NBLOCKS - 1) / NBLOCKS;

    // Prologue: fill the pipeline.
    if (tid == 0) {
        int pre = nloc < DEPTH ? nloc : DEPTH;
        for (int i = 0; i < pre; i++) {
            int g = bx + i * NBLOCKS;
            uint32_t mbar = smem_base + SMEM_BAR_OFF + i * 8;
            uint32_t dstL = smem_base + i * SLOT_BYTES;
            uint32_t dstT = dstL + LOGIT_BYTES;
            MBAR_EXPECT_TX(mbar, SLOT_BYTES);
            BULK_G2S(dstL, (const void*)(logits + (size_t)g * STAGE_ELEMS * 8), LOGIT_BYTES, mbar);
            BULK_G2S(dstT, (const void*)(targets + (size_t)g * STAGE_ELEMS), TGT_BYTES, mbar);
        }
    }

    const int el_off = (lane >> 1) + ((lane & 1) << 4);

    for (int sl = 0; sl < nloc; sl++) {
        int slot = sl & (DEPTH - 1);
        uint32_t parity = (sl / DEPTH) & 1;
        uint32_t mbar = smem_base + SMEM_BAR_OFF + slot * 8;
        mbar_wait_parity(mbar, parity);

        const float4* sL = (const float4*)(smem + slot * SLOT_BYTES);
        const int*    sT = (const int*)(smem + slot * SLOT_BYTES + LOGIT_BYTES);

        // 16 warps x 64 elements = 1024 per stage.
        int base = wid * 64;
        float4 A0 = sL[2 * base +       lane];
        float4 B0 = sL[2 * base + 32 +  lane];
        float4 A1 = sL[2 * base + 64 +  lane];
        float4 B1 = sL[2 * base + 96 +  lane];
        int t0 = sT[base +      el_off];
        int t1 = sT[base + 32 + el_off];

        process32(A0, B0, t0, lane, sgn, cL, cH);
        process32(A1, B1, t1, lane, sgn, cL, cH);

        __syncthreads();   // everyone done with this slot

        if (tid == 0 && sl + DEPTH < nloc) {
            int g = bx + (sl + DEPTH) * NBLOCKS;
            uint32_t dstL = smem_base + slot * SLOT_BYTES;
            uint32_t dstT = dstL + LOGIT_BYTES;
            MBAR_EXPECT_TX(mbar, SLOT_BYTES);
            BULK_G2S(dstL, (const void*)(logits + (size_t)g * STAGE_ELEMS * 8), LOGIT_BYTES, mbar);
            BULK_G2S(dstT, (const void*)(targets + (size_t)g * STAGE_ELEMS), TGT_BYTES, mbar);
        }
    }

    // Per-warp flush: 2 shared atomics per lane, once per kernel.
    if (cL) atomicAdd(&s_cm[lane], cL);
    if (cH) atomicAdd(&s_cm[lane + 32], cH);
    __syncthreads();

    // Block flush to global.
    if (tid < 64) {
        unsigned int c = s_cm[tid];
        if (c) atomicAdd(&g_cm[tid], c);
    }

    // Ticket: last block to arrive finalizes.
    __threadfence();
    __syncthreads();
    if (tid == 0) {
        unsigned int rank = atomicAdd(&g_done, 1u);
        s_is_last = (rank == gridDim.x - 1);
    }
    __syncthreads();
    if (!s_is_last) return;

    if (tid == 0) {
        __threadfence();

        float cm[64];
        float n = 0.0f;
        #pragma unroll
        for (int i = 0; i < 64; i++) {
            unsigned int c = atomicAdd(&g_cm[i], 0u);
            cm[i] = (float)c;
            n += cm[i];
        }

        float loss;
        if (n == 0.0f) {
            loss = 0.0f;
        } else {
            float inv_n = 1.0f / n;
            #pragma unroll
            for (int i = 0; i < 64; i++) cm[i] *= inv_n;

            float mt[8], mp[8];
            #pragma unroll
            for (int i = 0; i < 8; i++) { mt[i] = 0.0f; mp[i] = 0.0f; }
            #pragma unroll
            for (int i = 0; i < 8; i++)
                #pragma unroll
                for (int jj = 0; jj < 8; jj++) {
                    mt[i] += cm[i * 8 + jj];
                    mp[jj] += cm[i * 8 + jj];
                }

            const float inv_d2 = 1.0f / 49.0f;
            float num = 0.0f, den = 0.0f;
            #pragma unroll
            for (int i = 0; i < 8; i++)
                #pragma unroll
                for (int jj = 0; jj < 8; jj++) {
                    float d = (float)(i - jj);
                    float w = 1.0f - d * d * inv_d2;
                    num += w * cm[i * 8 + jj];
                    den += w * mt[i] * mp[jj];
                }

            float qwk = (den == 0.0f) ? 0.0f : (num / den);
            loss = 1.0f - qwk;
        }
        out[0] = loss;

        #pragma unroll
        for (int i = 0; i < 64; i++) g_cm[i] = 0u;
        g_done = 0u;
        __threadfence();
    }
}

extern "C" void kernel_launch(void* const* d_in, const int* in_sizes, int n_in,
                              void* d_out, int out_size) {
    const float* logits = (const float*)d_in[0];
    const int* targets = (const int*)d_in[1];
    float* out = (float*)d_out;
    int n_elems = in_sizes[1];       // 2048*4096, multiple of 1024

    cudaFuncSetAttribute(qwk_tma_kernel,
                         cudaFuncAttributeMaxDynamicSharedMemorySize, SMEM_TOTAL);
    qwk_tma_kernel<<<NBLOCKS, NTHREADS, SMEM_TOTAL>>>(logits, targets, out, n_elems);
}